// round 2
// baseline (speedup 1.0000x reference)
#include <cuda_runtime.h>
#include <cuda_bf16.h>
#include <cstdint>

// The reference pipeline is mathematically the identity map:
//   recomb = [mag*cos(ph), mag*sin(ph)] == [re, im] exactly;
//   INV_BASIS = pinv(scale*FB).T * w where pinv(scale*FB) is a LEFT inverse
//   of the full-column-rank forward basis, so per-frame
//   y_t = (1/scale) * w^2 .* x_pad_t; overlap-add gives (1/scale)*ws[n]*x_pad[n];
//   the final divide-by-ws and *scale yields x_pad; cropping [pad:-pad]
//   returns the original input. Verified: rel_err 2.9e-07 (reference fp noise).
//
// Output (32,1,160000) == input (32,160000). Optimal kernel = one D2D copy.
// cudaMemcpyAsync D2D is graph-capturable (memcpy node) and uses the
// driver's tuned copy kernel (wide vectors, high per-thread MLP), which
// saturates the ~6300 B/cyc LTS ceiling better than a 1-float4-per-thread
// hand copy (measured 2.38 TB/s, 30% DRAM).

extern "C" void kernel_launch(void* const* d_in, const int* in_sizes, int n_in,
                              void* d_out, int out_size) {
    const float* in = (const float*)d_in[0];
    float* out = (float*)d_out;
    size_t bytes = (size_t)out_size * sizeof(float);  // 32*160000*4 = 20.48 MB
    cudaMemcpyAsync(out, in, bytes, cudaMemcpyDeviceToDevice, 0);
}